// round 15
// baseline (speedup 1.0000x reference)
#include <cuda_runtime.h>
#include <cstdint>
#include <math.h>

// ---------------------------------------------------------------------------
// Round 14: attn -> 8 warps / 256 threads. S warp grid 2(m)x4(n), PV grid
// 4(m)x2(n): cuts K-fragment redundancy 4->2 and Ps-fragment redundancy 4->2
// (-192KB smem reads per tile, ~20% of all L1 bytes). Everything else = r13.
// ---------------------------------------------------------------------------

constexpr int TQ  = 2048;
constexpr int TK  = 2048;
constexpr int BSZ = 4;
constexpr int CDIM = 1024;
constexpr int H   = 16;
constexpr int DH  = 64;
constexpr int BH  = BSZ * H;            // 64
constexpr int MPROJ = TQ * BSZ;         // 8192

__device__ __align__(16) float g_aq[(size_t)MPROJ * CDIM];     // perm+rounded
__device__ __align__(16) float g_ak[(size_t)MPROJ * CDIM];
__device__ __align__(16) float g_av[(size_t)MPROJ * CDIM];
__device__ __align__(16) float g_w[4][(size_t)CDIM * CDIM];    // [n][p(k)] rounded
__device__ __align__(16) float g_q[(size_t)BH * TQ * DH];      // rounded
__device__ __align__(16) float g_k[(size_t)BH * TK * DH];
__device__ __align__(16) float g_v[(size_t)BH * TK * DH];
__device__ __align__(16) float g_x[(size_t)BH * TQ * DH];      // perm+rounded
__device__ float g_linv[(size_t)BH * TQ];

__device__ __forceinline__ unsigned f2tf(float x) {
    unsigned r; asm("cvt.rna.tf32.f32 %0, %1;" : "=r"(r) : "f"(x)); return r;
}
__device__ __forceinline__ float roundtf(float x) {
    return __uint_as_float(f2tf(x));
}
__device__ __forceinline__ void mma8(float* d, const unsigned* a, const unsigned* b) {
    asm volatile(
        "mma.sync.aligned.m16n8k8.row.col.f32.tf32.tf32.f32 "
        "{%0,%1,%2,%3},{%4,%5,%6,%7},{%8,%9},{%0,%1,%2,%3};"
        : "+f"(d[0]), "+f"(d[1]), "+f"(d[2]), "+f"(d[3])
        : "r"(a[0]), "r"(a[1]), "r"(a[2]), "r"(a[3]), "r"(b[0]), "r"(b[1]));
}
__device__ __forceinline__ unsigned sptr(const void* p) {
    return (unsigned)__cvta_generic_to_shared(p);
}
#define CP16(dst_u32, src_ptr) \
    asm volatile("cp.async.cg.shared.global [%0], [%1], 16;" :: "r"(dst_u32), "l"(src_ptr))
#define CP_COMMIT() asm volatile("cp.async.commit_group;")

// ---------------------------------------------------------------------------
// prep kernels
// ---------------------------------------------------------------------------
__global__ __launch_bounds__(256)
void round_inputs_kernel(const float* __restrict__ q, const float* __restrict__ k,
                         const float* __restrict__ v)
{
    const int z = blockIdx.z;
    const float4* src = (const float4*)((z == 0) ? q : (z == 1) ? k : v);
    float* dst = (z == 0) ? g_aq : (z == 1) ? g_ak : g_av;
    size_t idx = (size_t)blockIdx.x * 256 + threadIdx.x;
    float4 a = src[idx];
    size_t m = idx >> 8;
    int kk = (int)(idx & 255) * 4;
    size_t base = m * CDIM + (kk & ~7) + ((kk >> 2) & 1);
    dst[base + 0] = roundtf(a.x);
    dst[base + 2] = roundtf(a.y);
    dst[base + 4] = roundtf(a.z);
    dst[base + 6] = roundtf(a.w);
}

__global__ __launch_bounds__(256)
void round_w_kernel(const float* __restrict__ W0, const float* __restrict__ W1,
                    const float* __restrict__ W2, const float* __restrict__ W3)
{
    __shared__ float t[32][33];
    const int z = blockIdx.z;
    const float* W = (z == 0) ? W0 : (z == 1) ? W1 : (z == 2) ? W2 : W3;
    float* out = g_w[z];
    const int bx = blockIdx.x * 32;   // n base
    const int by = blockIdx.y * 32;   // k base
    const int tx = threadIdx.x, ty = threadIdx.y;
#pragma unroll
    for (int j = 0; j < 4; j++)
        t[ty + j * 8][tx] = W[(size_t)(by + ty + j * 8) * CDIM + bx + tx];
    __syncthreads();
    const int pk = (tx & ~7) | ((tx & 3) << 1) | ((tx >> 2) & 1);
#pragma unroll
    for (int j = 0; j < 4; j++)
        out[(size_t)(bx + ty + j * 8) * CDIM + by + pk] = roundtf(t[tx][ty + j * 8]);
}

// ---------------------------------------------------------------------------
// proj mma core (stride 40, conflict-free LDS.64)
// ---------------------------------------------------------------------------
__device__ __forceinline__
void proj_mma_step(float acc[4][4][4], const unsigned* AsF, const unsigned* BsF,
                   int wm, int wn, int gid, int tig)
{
#pragma unroll
    for (int kk = 0; kk < 32; kk += 8) {
        unsigned af[4][4], bf[4][2];
#pragma unroll
        for (int mi = 0; mi < 4; mi++) {
            int rb = wm * 64 + mi * 16;
            uint2 lo = *(const uint2*)&AsF[(rb + gid)     * 40 + kk + tig * 2];
            uint2 hi = *(const uint2*)&AsF[(rb + gid + 8) * 40 + kk + tig * 2];
            af[mi][0] = lo.x; af[mi][1] = hi.x; af[mi][2] = lo.y; af[mi][3] = hi.y;
        }
#pragma unroll
        for (int ni = 0; ni < 4; ni++) {
            int cb = wn * 32 + ni * 8;
            uint2 u = *(const uint2*)&BsF[(cb + gid) * 40 + kk + tig * 2];
            bf[ni][0] = u.x; bf[ni][1] = u.y;
        }
#pragma unroll
        for (int mi = 0; mi < 4; mi++)
#pragma unroll
            for (int ni = 0; ni < 4; ni++) mma8(acc[mi][ni], af[mi], bf[ni]);
    }
}

template<bool GATHER>
__device__ __forceinline__
void proj_issue(unsigned asm_, unsigned bsm_, const float* __restrict__ A,
                const float* __restrict__ Wt, int m0, int n0, int k0, int tid)
{
#pragma unroll
    for (int i = 0; i < 4; i++) {
        int li = tid + i * 256;
        int r = li >> 3, c = li & 7;
        const float* src;
        if (!GATHER) {
            src = A + (size_t)(m0 + r) * CDIM + k0 + c * 4;
        } else {
            int m = m0 + r, t = m >> 2, b = m & 3;
            int k = k0 + c * 4, h = k >> 6, d = k & 63;
            src = g_x + (((size_t)(b * H + h)) * TQ + t) * DH + d;
        }
        CP16(asm_ + (r * 40 + c * 4) * 4, src);
    }
#pragma unroll
    for (int i = 0; i < 4; i++) {
        int li = tid + i * 256;
        int r = li >> 3, c = li & 7;
        CP16(bsm_ + (r * 40 + c * 4) * 4, Wt + (size_t)(n0 + r) * CDIM + k0 + c * 4);
    }
    CP_COMMIT();
}

struct ProjSmem { unsigned As[2][128 * 40]; unsigned Bs[2][128 * 40]; };
constexpr int PROJ_SMEM = sizeof(ProjSmem);   // 81920

template<bool GATHER>
__device__ __forceinline__
void proj_tile(ProjSmem* sm, const float* __restrict__ A, const float* __restrict__ Wt,
               float acc[4][4][4], int m0, int n0, int tid,
               int wm, int wn, int gid, int tig)
{
    proj_issue<GATHER>(sptr(sm->As[0]), sptr(sm->Bs[0]), A, Wt, m0, n0, 0, tid);
    for (int it = 0; it < 32; it++) {
        if (it < 31)
            proj_issue<GATHER>(sptr(sm->As[(it + 1) & 1]), sptr(sm->Bs[(it + 1) & 1]),
                               A, Wt, m0, n0, (it + 1) * 32, tid);
        if (it < 31) asm volatile("cp.async.wait_group 1;");
        else         asm volatile("cp.async.wait_group 0;");
        __syncthreads();
        proj_mma_step(acc, sm->As[it & 1], sm->Bs[it & 1], wm, wn, gid, tig);
        __syncthreads();
    }
}

__global__ __launch_bounds__(256, 2)
void qkv_proj_kernel(const float* __restrict__ bq, const float* __restrict__ bk,
                     const float* __restrict__ bv)
{
    extern __shared__ char smraw[];
    ProjSmem* sm = (ProjSmem*)smraw;
    const int z = blockIdx.z;
    const float* A    = (z == 0) ? g_aq : (z == 1) ? g_ak : g_av;
    const float* Wt   = g_w[z];
    const float* bias = (z == 0) ? bq : (z == 1) ? bk : bv;
    float* dst        = (z == 0) ? g_q : (z == 1) ? g_k : g_v;
    const float scale = (z == 0) ? 0.125f : 1.f;

    const int tid = threadIdx.x, lane = tid & 31, wid = tid >> 5;
    const int gid = lane >> 2, tig = lane & 3;
    const int wm = wid >> 2, wn = wid & 3;
    const int m0 = blockIdx.y * 128, n0 = blockIdx.x * 128;

    float acc[4][4][4] = {};
    proj_tile<false>(sm, A, Wt, acc, m0, n0, tid, wm, wn, gid, tig);

#pragma unroll
    for (int mi = 0; mi < 4; mi++)
#pragma unroll
        for (int hl = 0; hl < 2; hl++) {
            int m = m0 + wm * 64 + mi * 16 + gid + hl * 8;
#pragma unroll
            for (int ni = 0; ni < 4; ni++) {
                int n = n0 + wn * 32 + ni * 8 + tig * 2;
                float2 v;
                v.x = roundtf((acc[mi][ni][hl * 2 + 0] + bias[n + 0]) * scale);
                v.y = roundtf((acc[mi][ni][hl * 2 + 1] + bias[n + 1]) * scale);
                int t = m >> 2, b = m & 3, h = n >> 6, d = n & 63;
                *(float2*)&dst[(((size_t)(b * H + h)) * TQ + t) * DH + d] = v;
            }
        }
}

// ---------------------------------------------------------------------------
// Heterogeneous epilogue: r==0 -> double-buffered out_proj tile; r>0 ->
// rescale 8 attn rows.
// ---------------------------------------------------------------------------
__global__ __launch_bounds__(256)
void epilogue_kernel(const float* __restrict__ bias, float* __restrict__ Out,
                     float* __restrict__ attn)
{
    const int g = blockIdx.x;
    const int p = g / 33, r = g % 33;
    if (r == 0) {
        extern __shared__ char smraw[];
        ProjSmem* sm = (ProjSmem*)smraw;
        const int tid = threadIdx.x, lane = tid & 31, wid = tid >> 5;
        const int gid = lane >> 2, tig = lane & 3;
        const int wm = wid >> 2, wn = wid & 3;
        const int m0 = (p >> 3) * 128, n0 = (p & 7) * 128;

        float acc[4][4][4] = {};
        proj_tile<true>(sm, nullptr, g_w[3], acc, m0, n0, tid, wm, wn, gid, tig);

#pragma unroll
        for (int mi = 0; mi < 4; mi++)
#pragma unroll
            for (int hl = 0; hl < 2; hl++) {
                int m = m0 + wm * 64 + mi * 16 + gid + hl * 8;
#pragma unroll
                for (int ni = 0; ni < 4; ni++) {
                    int n = n0 + wn * 32 + ni * 8 + tig * 2;
                    float2 v;
                    v.x = acc[mi][ni][hl * 2 + 0] + bias[n + 0];
                    v.y = acc[mi][ni][hl * 2 + 1] + bias[n + 1];
                    *(float2*)&Out[(size_t)m * CDIM + n] = v;
                }
            }
    } else {
        const size_t row0 = ((size_t)p * 32 + (r - 1)) * 8;
        const int tid = threadIdx.x;
#pragma unroll
        for (int rr = 0; rr < 8; rr++) {
            const size_t row = row0 + rr;
            const float inv = g_linv[row];
            float4* pr = (float4*)(attn + row * (size_t)TK);
            float4 v0 = pr[tid], v1 = pr[tid + 256];
            v0.x *= inv; v0.y *= inv; v0.z *= inv; v0.w *= inv;
            v1.x *= inv; v1.y *= inv; v1.z *= inv; v1.w *= inv;
            pr[tid] = v0; pr[tid + 256] = v1;
        }
    }
}

// ---------------------------------------------------------------------------
// attn_fused (256 threads, 8 warps).
// S phase: warp grid 2(m) x 4(n), warp tile 64m x 32n  (Q x4, K x2 redund.)
// PV phase: warp grid 4(m) x 2(n), warp tile 32m x 32n (Ps x2, V x4 redund.)
// Strides: Qs 72, Ks 68, Vs 72, Ps 136 (all conflict-free per r12/r13 model).
// smem u32 map:
//   Qs 0..9216 | Ks0 9216..17920 | Ks1 17920..26624 | Vs 26624..35840 |
//   Ps 35840..53248 | mskAll 53248..55296 | red 55296..55808 | sm_inv ..55936
// ---------------------------------------------------------------------------
constexpr int AT_SMEM = 55936 * 4;   // 223744 B

__global__ __launch_bounds__(256, 1)
void attn_fused_kernel(const unsigned char* __restrict__ mask,
                       float* __restrict__ attn)
{
    extern __shared__ unsigned smem_u[];
    unsigned* Qs  = smem_u;                        // [128][72] perm tf32
    unsigned* Ks0 = smem_u + 9216;                 // [n:128][d:64] s68
    unsigned* Ks1 = smem_u + 17920;
    unsigned* Vs  = smem_u + 26624;                // [n:128][d:64] s72
    unsigned* Ps  = smem_u + 35840;                // [128][136] tf32 perm
    float* mskAll = (float*)(smem_u + 53248);      // [2048]
    float* red    = (float*)(smem_u + 55296);      // [4][128]
    float* sm_inv = (float*)(smem_u + 55808);

    const int tid = threadIdx.x, lane = tid & 31, wid = tid >> 5;
    const int gid = lane >> 2, tig = lane & 3;
    const int wm = wid >> 2, wn = wid & 3;         // S: 2 x 4
    const int wm2 = wid >> 1, wn2 = wid & 1;       // PV: 4 x 2
    const int m0 = blockIdx.x * 128, bh = blockIdx.y, b = bh >> 4;

    const float* kbase = g_k + (size_t)bh * TK * DH;
    const float* vbase = g_v + (size_t)bh * TK * DH;

#pragma unroll
    for (int i = 0; i < 8; i++) {
        int li = tid + i * 256;
        int r = li >> 4, c = li & 15;
        uint4 a = *(const uint4*)&g_q[((size_t)bh * TQ + m0 + r) * DH + c * 4];
        unsigned* q = &Qs[r * 72 + (c >> 1) * 8 + (c & 1)];
        q[0] = a.x; q[2] = a.y; q[4] = a.z; q[6] = a.w;
    }
#pragma unroll
    for (int i = 0; i < 8; i++) {
        int idx = tid + i * 256;
        mskAll[idx] = mask[(size_t)b * TK + idx] ? -INFINITY : 0.f;
    }
    {
        const unsigned ksm = sptr(Ks0);
#pragma unroll
        for (int j = 0; j < 8; j++) {
            int li = tid + j * 256;
            int r = li >> 4, c16 = li & 15;
            CP16(ksm + (r * 68 + c16 * 4) * 4, kbase + r * 64 + c16 * 4);
        }
        CP_COMMIT();
    }

    float acco[2][4][4] = {};     // PV: 2 mi x 4 ni (32m x 32n warp tile)
    float lsum[4][2] = {};        // S: 4 mi x 2 hl
    const int perm0 = ((2 * tig) & 3) * 2 + (tig >> 1);

    for (int nt = 0; nt < 16; nt++) {
        const int n0 = nt * 128;
        __syncthreads();

        {
            const unsigned vsm = sptr(Vs);
#pragma unroll
            for (int j = 0; j < 8; j++) {
                int li = tid + j * 256;
                int r = li >> 4, c16 = li & 15;
                CP16(vsm + (r * 72 + c16 * 4) * 4, vbase + (size_t)(n0 + r) * 64 + c16 * 4);
            }
            CP_COMMIT();
        }
        if (nt < 15) {
            unsigned* Kn = ((nt + 1) & 1) ? Ks1 : Ks0;
            const unsigned ksm = sptr(Kn);
#pragma unroll
            for (int j = 0; j < 8; j++) {
                int li = tid + j * 256;
                int r = li >> 4, c16 = li & 15;
                CP16(ksm + (r * 68 + c16 * 4) * 4,
                     kbase + (size_t)(n0 + 128 + r) * 64 + c16 * 4);
            }
            CP_COMMIT();
        }

        if (nt < 15) asm volatile("cp.async.wait_group 2;");
        else         asm volatile("cp.async.wait_group 1;");
        __syncthreads();

        const unsigned* Ksu = (nt & 1) ? Ks1 : Ks0;

        // ---- S = Q @ K^T  (warp tile 64m x 32n)
        float acc[4][4][4] = {};
#pragma unroll
        for (int kk = 0; kk < 64; kk += 8) {
            unsigned af[4][4], bf[4][2];
#pragma unroll
            for (int mi = 0; mi < 4; mi++) {
                int rb = wm * 64 + mi * 16;
                uint2 lo = *(const uint2*)&Qs[(rb + gid)     * 72 + kk + tig * 2];
                uint2 hi = *(const uint2*)&Qs[(rb + gid + 8) * 72 + kk + tig * 2];
                af[mi][0] = lo.x; af[mi][1] = hi.x; af[mi][2] = lo.y; af[mi][3] = hi.y;
            }
#pragma unroll
            for (int ni = 0; ni < 4; ni++) {
                int cb = wn * 32 + ni * 8;
                bf[ni][0] = Ksu[(cb + gid) * 68 + kk + tig];
                bf[ni][1] = Ksu[(cb + gid) * 68 + kk + tig + 4];
            }
#pragma unroll
            for (int mi = 0; mi < 4; mi++)
#pragma unroll
                for (int ni = 0; ni < 4; ni++) mma8(acc[mi][ni], af[mi], bf[ni]);
        }

        float mk[4][2];
#pragma unroll
        for (int ni = 0; ni < 4; ni++) {
            float2 mm = *(const float2*)&mskAll[n0 + wn * 32 + ni * 8 + 2 * tig];
            mk[ni][0] = mm.x; mk[ni][1] = mm.y;
        }

        // ---- E = exp(S+mask): attn write (unnormalized), rowsum, Ps stage
#pragma unroll
        for (int mi = 0; mi < 4; mi++) {
            int rb = wm * 64 + mi * 16;
#pragma unroll
            for (int hl = 0; hl < 2; hl++) {
                int row = rb + gid + hl * 8;
                float* arow = attn + ((size_t)bh * TQ + m0 + row) * TK + n0;
                float ls = 0.f;
#pragma unroll
                for (int ni = 0; ni < 4; ni++) {
                    int cb = wn * 32 + ni * 8;
                    float p0 = __expf(acc[mi][ni][hl * 2]     + mk[ni][0]);
                    float p1 = __expf(acc[mi][ni][hl * 2 + 1] + mk[ni][1]);
                    *(float2*)&arow[cb + 2 * tig] = make_float2(p0, p1);
                    unsigned* pp = &Ps[row * 136 + cb + perm0];
                    pp[0] = f2tf(p0); pp[2] = f2tf(p1);
                    ls += p0 + p1;
                }
                lsum[mi][hl] += ls;
            }
        }

        if (nt < 15) asm volatile("cp.async.wait_group 1;");
        else         asm volatile("cp.async.wait_group 0;");
        __syncthreads();

        // ---- O += E @ V   (warp tile 32m x 32n, k = 128)
#pragma unroll
        for (int kk = 0; kk < 128; kk += 8) {
            unsigned af[2][4], bf[4][2];
#pragma unroll
            for (int mi = 0; mi < 2; mi++) {
                int rb = wm2 * 32 + mi * 16;
                uint2 lo = *(const uint2*)&Ps[(rb + gid)     * 136 + kk + tig * 2];
                uint2 hi = *(const uint2*)&Ps[(rb + gid + 8) * 136 + kk + tig * 2];
                af[mi][0] = lo.x; af[mi][1] = hi.x; af[mi][2] = lo.y; af[mi][3] = hi.y;
            }
#pragma unroll
            for (int ni = 0; ni < 4; ni++) {
                int cb = wn2 * 32 + ni * 8;
                bf[ni][0] = Vs[(kk + tig)     * 72 + cb + gid];
                bf[ni][1] = Vs[(kk + tig + 4) * 72 + cb + gid];
            }
#pragma unroll
            for (int mi = 0; mi < 2; mi++)
#pragma unroll
                for (int ni = 0; ni < 4; ni++) mma8(acco[mi][ni], af[mi], bf[ni]);
        }
    }

    // ---- rowsum -> 1/l  (S ownership: wn in 0..3, rows wm*64+mi*16+gid+hl*8)
    __syncthreads();
#pragma unroll
    for (int mi = 0; mi < 4; mi++)
#pragma unroll
        for (int hl = 0; hl < 2; hl++) {
            float v = lsum[mi][hl];
            v += __shfl_xor_sync(~0u, v, 1);
            v += __shfl_xor_sync(~0u, v, 2);
            if (tig == 0) red[wn * 128 + wm * 64 + mi * 16 + gid + hl * 8] = v;
        }
    __syncthreads();
    if (tid < 128) {
        float inv = 1.f / (red[tid] + red[128 + tid] + red[256 + tid] + red[384 + tid]);
        sm_inv[tid] = inv;
        g_linv[(size_t)bh * TQ + m0 + tid] = inv;
    }
    __syncthreads();

    // ---- O normalize, tf32-round, PERMUTED store -> g_x (PV ownership)
#pragma unroll
    for (int mi = 0; mi < 2; mi++)
#pragma unroll
        for (int hl = 0; hl < 2; hl++) {
            int row = wm2 * 32 + mi * 16 + gid + hl * 8;
            float inv = sm_inv[row];
#pragma unroll
            for (int ni = 0; ni < 4; ni++) {
                int c = wn2 * 32 + ni * 8 + tig * 2;
                int j0 = (c & ~7) + ((c & 3) << 1) + ((c >> 2) & 1);
                float* xr = &g_x[((size_t)bh * TQ + m0 + row) * DH];
                xr[j0]     = roundtf(acco[mi][ni][hl * 2] * inv);
                xr[j0 + 2] = roundtf(acco[mi][ni][hl * 2 + 1] * inv);
            }
        }
}

// ---------------------------------------------------------------------------
extern "C" void kernel_launch(void* const* d_in, const int* in_sizes, int n_in,
                              void* d_out, int out_size)
{
    const float* query = (const float*)d_in[0];
    const float* key   = (const float*)d_in[1];
    const float* value = (const float*)d_in[2];
    const unsigned char* mask = (const unsigned char*)d_in[3];
    const float* Wq = (const float*)d_in[4];
    const float* bq = (const float*)d_in[5];
    const float* Wk = (const float*)d_in[6];
    const float* bk = (const float*)d_in[7];
    const float* Wv = (const float*)d_in[8];
    const float* bv = (const float*)d_in[9];
    const float* Wo = (const float*)d_in[10];
    const float* bo = (const float*)d_in[11];

    float* out_x = (float*)d_out;                       // [2048,4,1024]
    float* attn  = out_x + (size_t)TQ * BSZ * CDIM;     // [64,2048,2048]

    cudaFuncSetAttribute(attn_fused_kernel,
                         cudaFuncAttributeMaxDynamicSharedMemorySize, AT_SMEM);
    cudaFuncSetAttribute(qkv_proj_kernel,
                         cudaFuncAttributeMaxDynamicSharedMemorySize, PROJ_SMEM);
    cudaFuncSetAttribute(epilogue_kernel,
                         cudaFuncAttributeMaxDynamicSharedMemorySize, PROJ_SMEM);

    round_inputs_kernel<<<dim3(MPROJ, 1, 3), 256>>>(query, key, value);
    round_w_kernel<<<dim3(32, 32, 4), dim3(32, 8)>>>(Wq, Wk, Wv, Wo);
    qkv_proj_kernel<<<dim3(8, 64, 3), 256, PROJ_SMEM>>>(bq, bk, bv);
    attn_fused_kernel<<<dim3(16, 64), 256, AT_SMEM>>>(mask, attn);
    epilogue_kernel<<<dim3(512 * 33), 256, PROJ_SMEM>>>(bo, out_x, attn);
}

// round 16
// speedup vs baseline: 1.0010x; 1.0010x over previous
#include <cuda_runtime.h>
#include <cstdint>
#include <math.h>

// ---------------------------------------------------------------------------
// Round 14: attn -> 8 warps / 256 threads. S warp grid 2(m)x4(n), PV grid
// 4(m)x2(n): cuts K-fragment redundancy 4->2 and Ps-fragment redundancy 4->2
// (-192KB smem reads per tile, ~20% of all L1 bytes). Everything else = r13.
// ---------------------------------------------------------------------------

constexpr int TQ  = 2048;
constexpr int TK  = 2048;
constexpr int BSZ = 4;
constexpr int CDIM = 1024;
constexpr int H   = 16;
constexpr int DH  = 64;
constexpr int BH  = BSZ * H;            // 64
constexpr int MPROJ = TQ * BSZ;         // 8192

__device__ __align__(16) float g_aq[(size_t)MPROJ * CDIM];     // perm+rounded
__device__ __align__(16) float g_ak[(size_t)MPROJ * CDIM];
__device__ __align__(16) float g_av[(size_t)MPROJ * CDIM];
__device__ __align__(16) float g_w[4][(size_t)CDIM * CDIM];    // [n][p(k)] rounded
__device__ __align__(16) float g_q[(size_t)BH * TQ * DH];      // rounded
__device__ __align__(16) float g_k[(size_t)BH * TK * DH];
__device__ __align__(16) float g_v[(size_t)BH * TK * DH];
__device__ __align__(16) float g_x[(size_t)BH * TQ * DH];      // perm+rounded
__device__ float g_linv[(size_t)BH * TQ];

__device__ __forceinline__ unsigned f2tf(float x) {
    unsigned r; asm("cvt.rna.tf32.f32 %0, %1;" : "=r"(r) : "f"(x)); return r;
}
__device__ __forceinline__ float roundtf(float x) {
    return __uint_as_float(f2tf(x));
}
__device__ __forceinline__ void mma8(float* d, const unsigned* a, const unsigned* b) {
    asm volatile(
        "mma.sync.aligned.m16n8k8.row.col.f32.tf32.tf32.f32 "
        "{%0,%1,%2,%3},{%4,%5,%6,%7},{%8,%9},{%0,%1,%2,%3};"
        : "+f"(d[0]), "+f"(d[1]), "+f"(d[2]), "+f"(d[3])
        : "r"(a[0]), "r"(a[1]), "r"(a[2]), "r"(a[3]), "r"(b[0]), "r"(b[1]));
}
__device__ __forceinline__ unsigned sptr(const void* p) {
    return (unsigned)__cvta_generic_to_shared(p);
}
#define CP16(dst_u32, src_ptr) \
    asm volatile("cp.async.cg.shared.global [%0], [%1], 16;" :: "r"(dst_u32), "l"(src_ptr))
#define CP_COMMIT() asm volatile("cp.async.commit_group;")

// ---------------------------------------------------------------------------
// prep kernels
// ---------------------------------------------------------------------------
__global__ __launch_bounds__(256)
void round_inputs_kernel(const float* __restrict__ q, const float* __restrict__ k,
                         const float* __restrict__ v)
{
    const int z = blockIdx.z;
    const float4* src = (const float4*)((z == 0) ? q : (z == 1) ? k : v);
    float* dst = (z == 0) ? g_aq : (z == 1) ? g_ak : g_av;
    size_t idx = (size_t)blockIdx.x * 256 + threadIdx.x;
    float4 a = src[idx];
    size_t m = idx >> 8;
    int kk = (int)(idx & 255) * 4;
    size_t base = m * CDIM + (kk & ~7) + ((kk >> 2) & 1);
    dst[base + 0] = roundtf(a.x);
    dst[base + 2] = roundtf(a.y);
    dst[base + 4] = roundtf(a.z);
    dst[base + 6] = roundtf(a.w);
}

__global__ __launch_bounds__(256)
void round_w_kernel(const float* __restrict__ W0, const float* __restrict__ W1,
                    const float* __restrict__ W2, const float* __restrict__ W3)
{
    __shared__ float t[32][33];
    const int z = blockIdx.z;
    const float* W = (z == 0) ? W0 : (z == 1) ? W1 : (z == 2) ? W2 : W3;
    float* out = g_w[z];
    const int bx = blockIdx.x * 32;   // n base
    const int by = blockIdx.y * 32;   // k base
    const int tx = threadIdx.x, ty = threadIdx.y;
#pragma unroll
    for (int j = 0; j < 4; j++)
        t[ty + j * 8][tx] = W[(size_t)(by + ty + j * 8) * CDIM + bx + tx];
    __syncthreads();
    const int pk = (tx & ~7) | ((tx & 3) << 1) | ((tx >> 2) & 1);
#pragma unroll
    for (int j = 0; j < 4; j++)
        out[(size_t)(bx + ty + j * 8) * CDIM + by + pk] = roundtf(t[tx][ty + j * 8]);
}

// ---------------------------------------------------------------------------
// proj mma core (stride 40, conflict-free LDS.64)
// ---------------------------------------------------------------------------
__device__ __forceinline__
void proj_mma_step(float acc[4][4][4], const unsigned* AsF, const unsigned* BsF,
                   int wm, int wn, int gid, int tig)
{
#pragma unroll
    for (int kk = 0; kk < 32; kk += 8) {
        unsigned af[4][4], bf[4][2];
#pragma unroll
        for (int mi = 0; mi < 4; mi++) {
            int rb = wm * 64 + mi * 16;
            uint2 lo = *(const uint2*)&AsF[(rb + gid)     * 40 + kk + tig * 2];
            uint2 hi = *(const uint2*)&AsF[(rb + gid + 8) * 40 + kk + tig * 2];
            af[mi][0] = lo.x; af[mi][1] = hi.x; af[mi][2] = lo.y; af[mi][3] = hi.y;
        }
#pragma unroll
        for (int ni = 0; ni < 4; ni++) {
            int cb = wn * 32 + ni * 8;
            uint2 u = *(const uint2*)&BsF[(cb + gid) * 40 + kk + tig * 2];
            bf[ni][0] = u.x; bf[ni][1] = u.y;
        }
#pragma unroll
        for (int mi = 0; mi < 4; mi++)
#pragma unroll
            for (int ni = 0; ni < 4; ni++) mma8(acc[mi][ni], af[mi], bf[ni]);
    }
}

template<bool GATHER>
__device__ __forceinline__
void proj_issue(unsigned asm_, unsigned bsm_, const float* __restrict__ A,
                const float* __restrict__ Wt, int m0, int n0, int k0, int tid)
{
#pragma unroll
    for (int i = 0; i < 4; i++) {
        int li = tid + i * 256;
        int r = li >> 3, c = li & 7;
        const float* src;
        if (!GATHER) {
            src = A + (size_t)(m0 + r) * CDIM + k0 + c * 4;
        } else {
            int m = m0 + r, t = m >> 2, b = m & 3;
            int k = k0 + c * 4, h = k >> 6, d = k & 63;
            src = g_x + (((size_t)(b * H + h)) * TQ + t) * DH + d;
        }
        CP16(asm_ + (r * 40 + c * 4) * 4, src);
    }
#pragma unroll
    for (int i = 0; i < 4; i++) {
        int li = tid + i * 256;
        int r = li >> 3, c = li & 7;
        CP16(bsm_ + (r * 40 + c * 4) * 4, Wt + (size_t)(n0 + r) * CDIM + k0 + c * 4);
    }
    CP_COMMIT();
}

struct ProjSmem { unsigned As[2][128 * 40]; unsigned Bs[2][128 * 40]; };
constexpr int PROJ_SMEM = sizeof(ProjSmem);   // 81920

template<bool GATHER>
__device__ __forceinline__
void proj_tile(ProjSmem* sm, const float* __restrict__ A, const float* __restrict__ Wt,
               float acc[4][4][4], int m0, int n0, int tid,
               int wm, int wn, int gid, int tig)
{
    proj_issue<GATHER>(sptr(sm->As[0]), sptr(sm->Bs[0]), A, Wt, m0, n0, 0, tid);
    for (int it = 0; it < 32; it++) {
        if (it < 31)
            proj_issue<GATHER>(sptr(sm->As[(it + 1) & 1]), sptr(sm->Bs[(it + 1) & 1]),
                               A, Wt, m0, n0, (it + 1) * 32, tid);
        if (it < 31) asm volatile("cp.async.wait_group 1;");
        else         asm volatile("cp.async.wait_group 0;");
        __syncthreads();
        proj_mma_step(acc, sm->As[it & 1], sm->Bs[it & 1], wm, wn, gid, tig);
        __syncthreads();
    }
}

__global__ __launch_bounds__(256, 2)
void qkv_proj_kernel(const float* __restrict__ bq, const float* __restrict__ bk,
                     const float* __restrict__ bv)
{
    extern __shared__ char smraw[];
    ProjSmem* sm = (ProjSmem*)smraw;
    const int z = blockIdx.z;
    const float* A    = (z == 0) ? g_aq : (z == 1) ? g_ak : g_av;
    const float* Wt   = g_w[z];
    const float* bias = (z == 0) ? bq : (z == 1) ? bk : bv;
    float* dst        = (z == 0) ? g_q : (z == 1) ? g_k : g_v;
    const float scale = (z == 0) ? 0.125f : 1.f;

    const int tid = threadIdx.x, lane = tid & 31, wid = tid >> 5;
    const int gid = lane >> 2, tig = lane & 3;
    const int wm = wid >> 2, wn = wid & 3;
    const int m0 = blockIdx.y * 128, n0 = blockIdx.x * 128;

    float acc[4][4][4] = {};
    proj_tile<false>(sm, A, Wt, acc, m0, n0, tid, wm, wn, gid, tig);

#pragma unroll
    for (int mi = 0; mi < 4; mi++)
#pragma unroll
        for (int hl = 0; hl < 2; hl++) {
            int m = m0 + wm * 64 + mi * 16 + gid + hl * 8;
#pragma unroll
            for (int ni = 0; ni < 4; ni++) {
                int n = n0 + wn * 32 + ni * 8 + tig * 2;
                float2 v;
                v.x = roundtf((acc[mi][ni][hl * 2 + 0] + bias[n + 0]) * scale);
                v.y = roundtf((acc[mi][ni][hl * 2 + 1] + bias[n + 1]) * scale);
                int t = m >> 2, b = m & 3, h = n >> 6, d = n & 63;
                *(float2*)&dst[(((size_t)(b * H + h)) * TQ + t) * DH + d] = v;
            }
        }
}

// ---------------------------------------------------------------------------
// Heterogeneous epilogue: r==0 -> double-buffered out_proj tile; r>0 ->
// rescale 8 attn rows.
// ---------------------------------------------------------------------------
__global__ __launch_bounds__(256)
void epilogue_kernel(const float* __restrict__ bias, float* __restrict__ Out,
                     float* __restrict__ attn)
{
    const int g = blockIdx.x;
    const int p = g / 33, r = g % 33;
    if (r == 0) {
        extern __shared__ char smraw[];
        ProjSmem* sm = (ProjSmem*)smraw;
        const int tid = threadIdx.x, lane = tid & 31, wid = tid >> 5;
        const int gid = lane >> 2, tig = lane & 3;
        const int wm = wid >> 2, wn = wid & 3;
        const int m0 = (p >> 3) * 128, n0 = (p & 7) * 128;

        float acc[4][4][4] = {};
        proj_tile<true>(sm, nullptr, g_w[3], acc, m0, n0, tid, wm, wn, gid, tig);

#pragma unroll
        for (int mi = 0; mi < 4; mi++)
#pragma unroll
            for (int hl = 0; hl < 2; hl++) {
                int m = m0 + wm * 64 + mi * 16 + gid + hl * 8;
#pragma unroll
                for (int ni = 0; ni < 4; ni++) {
                    int n = n0 + wn * 32 + ni * 8 + tig * 2;
                    float2 v;
                    v.x = acc[mi][ni][hl * 2 + 0] + bias[n + 0];
                    v.y = acc[mi][ni][hl * 2 + 1] + bias[n + 1];
                    *(float2*)&Out[(size_t)m * CDIM + n] = v;
                }
            }
    } else {
        const size_t row0 = ((size_t)p * 32 + (r - 1)) * 8;
        const int tid = threadIdx.x;
#pragma unroll
        for (int rr = 0; rr < 8; rr++) {
            const size_t row = row0 + rr;
            const float inv = g_linv[row];
            float4* pr = (float4*)(attn + row * (size_t)TK);
            float4 v0 = pr[tid], v1 = pr[tid + 256];
            v0.x *= inv; v0.y *= inv; v0.z *= inv; v0.w *= inv;
            v1.x *= inv; v1.y *= inv; v1.z *= inv; v1.w *= inv;
            pr[tid] = v0; pr[tid + 256] = v1;
        }
    }
}

// ---------------------------------------------------------------------------
// attn_fused (256 threads, 8 warps).
// S phase: warp grid 2(m) x 4(n), warp tile 64m x 32n  (Q x4, K x2 redund.)
// PV phase: warp grid 4(m) x 2(n), warp tile 32m x 32n (Ps x2, V x4 redund.)
// Strides: Qs 72, Ks 68, Vs 72, Ps 136 (all conflict-free per r12/r13 model).
// smem u32 map:
//   Qs 0..9216 | Ks0 9216..17920 | Ks1 17920..26624 | Vs 26624..35840 |
//   Ps 35840..53248 | mskAll 53248..55296 | red 55296..55808 | sm_inv ..55936
// ---------------------------------------------------------------------------
constexpr int AT_SMEM = 55936 * 4;   // 223744 B

__global__ __launch_bounds__(256, 1)
void attn_fused_kernel(const unsigned char* __restrict__ mask,
                       float* __restrict__ attn)
{
    extern __shared__ unsigned smem_u[];
    unsigned* Qs  = smem_u;                        // [128][72] perm tf32
    unsigned* Ks0 = smem_u + 9216;                 // [n:128][d:64] s68
    unsigned* Ks1 = smem_u + 17920;
    unsigned* Vs  = smem_u + 26624;                // [n:128][d:64] s72
    unsigned* Ps  = smem_u + 35840;                // [128][136] tf32 perm
    float* mskAll = (float*)(smem_u + 53248);      // [2048]
    float* red    = (float*)(smem_u + 55296);      // [4][128]
    float* sm_inv = (float*)(smem_u + 55808);

    const int tid = threadIdx.x, lane = tid & 31, wid = tid >> 5;
    const int gid = lane >> 2, tig = lane & 3;
    const int wm = wid >> 2, wn = wid & 3;         // S: 2 x 4
    const int wm2 = wid >> 1, wn2 = wid & 1;       // PV: 4 x 2
    const int m0 = blockIdx.x * 128, bh = blockIdx.y, b = bh >> 4;

    const float* kbase = g_k + (size_t)bh * TK * DH;
    const float* vbase = g_v + (size_t)bh * TK * DH;

#pragma unroll
    for (int i = 0; i < 8; i++) {
        int li = tid + i * 256;
        int r = li >> 4, c = li & 15;
        uint4 a = *(const uint4*)&g_q[((size_t)bh * TQ + m0 + r) * DH + c * 4];
        unsigned* q = &Qs[r * 72 + (c >> 1) * 8 + (c & 1)];
        q[0] = a.x; q[2] = a.y; q[4] = a.z; q[6] = a.w;
    }
#pragma unroll
    for (int i = 0; i < 8; i++) {
        int idx = tid + i * 256;
        mskAll[idx] = mask[(size_t)b * TK + idx] ? -INFINITY : 0.f;
    }
    {
        const unsigned ksm = sptr(Ks0);
#pragma unroll
        for (int j = 0; j < 8; j++) {
            int li = tid + j * 256;
            int r = li >> 4, c16 = li & 15;
            CP16(ksm + (r * 68 + c16 * 4) * 4, kbase + r * 64 + c16 * 4);
        }
        CP_COMMIT();
    }

    float acco[2][4][4] = {};     // PV: 2 mi x 4 ni (32m x 32n warp tile)
    float lsum[4][2] = {};        // S: 4 mi x 2 hl
    const int perm0 = ((2 * tig) & 3) * 2 + (tig >> 1);

    for (int nt = 0; nt < 16; nt++) {
        const int n0 = nt * 128;
        __syncthreads();

        {
            const unsigned vsm = sptr(Vs);
#pragma unroll
            for (int j = 0; j < 8; j++) {
                int li = tid + j * 256;
                int r = li >> 4, c16 = li & 15;
                CP16(vsm + (r * 72 + c16 * 4) * 4, vbase + (size_t)(n0 + r) * 64 + c16 * 4);
            }
            CP_COMMIT();
        }
        if (nt < 15) {
            unsigned* Kn = ((nt + 1) & 1) ? Ks1 : Ks0;
            const unsigned ksm = sptr(Kn);
#pragma unroll
            for (int j = 0; j < 8; j++) {
                int li = tid + j * 256;
                int r = li >> 4, c16 = li & 15;
                CP16(ksm + (r * 68 + c16 * 4) * 4,
                     kbase + (size_t)(n0 + 128 + r) * 64 + c16 * 4);
            }
            CP_COMMIT();
        }

        if (nt < 15) asm volatile("cp.async.wait_group 2;");
        else         asm volatile("cp.async.wait_group 1;");
        __syncthreads();

        const unsigned* Ksu = (nt & 1) ? Ks1 : Ks0;

        // ---- S = Q @ K^T  (warp tile 64m x 32n)
        float acc[4][4][4] = {};
#pragma unroll
        for (int kk = 0; kk < 64; kk += 8) {
            unsigned af[4][4], bf[4][2];
#pragma unroll
            for (int mi = 0; mi < 4; mi++) {
                int rb = wm * 64 + mi * 16;
                uint2 lo = *(const uint2*)&Qs[(rb + gid)     * 72 + kk + tig * 2];
                uint2 hi = *(const uint2*)&Qs[(rb + gid + 8) * 72 + kk + tig * 2];
                af[mi][0] = lo.x; af[mi][1] = hi.x; af[mi][2] = lo.y; af[mi][3] = hi.y;
            }
#pragma unroll
            for (int ni = 0; ni < 4; ni++) {
                int cb = wn * 32 + ni * 8;
                bf[ni][0] = Ksu[(cb + gid) * 68 + kk + tig];
                bf[ni][1] = Ksu[(cb + gid) * 68 + kk + tig + 4];
            }
#pragma unroll
            for (int mi = 0; mi < 4; mi++)
#pragma unroll
                for (int ni = 0; ni < 4; ni++) mma8(acc[mi][ni], af[mi], bf[ni]);
        }

        float mk[4][2];
#pragma unroll
        for (int ni = 0; ni < 4; ni++) {
            float2 mm = *(const float2*)&mskAll[n0 + wn * 32 + ni * 8 + 2 * tig];
            mk[ni][0] = mm.x; mk[ni][1] = mm.y;
        }

        // ---- E = exp(S+mask): attn write (unnormalized), rowsum, Ps stage
#pragma unroll
        for (int mi = 0; mi < 4; mi++) {
            int rb = wm * 64 + mi * 16;
#pragma unroll
            for (int hl = 0; hl < 2; hl++) {
                int row = rb + gid + hl * 8;
                float* arow = attn + ((size_t)bh * TQ + m0 + row) * TK + n0;
                float ls = 0.f;
#pragma unroll
                for (int ni = 0; ni < 4; ni++) {
                    int cb = wn * 32 + ni * 8;
                    float p0 = __expf(acc[mi][ni][hl * 2]     + mk[ni][0]);
                    float p1 = __expf(acc[mi][ni][hl * 2 + 1] + mk[ni][1]);
                    *(float2*)&arow[cb + 2 * tig] = make_float2(p0, p1);
                    unsigned* pp = &Ps[row * 136 + cb + perm0];
                    pp[0] = f2tf(p0); pp[2] = f2tf(p1);
                    ls += p0 + p1;
                }
                lsum[mi][hl] += ls;
            }
        }

        if (nt < 15) asm volatile("cp.async.wait_group 1;");
        else         asm volatile("cp.async.wait_group 0;");
        __syncthreads();

        // ---- O += E @ V   (warp tile 32m x 32n, k = 128)
#pragma unroll
        for (int kk = 0; kk < 128; kk += 8) {
            unsigned af[2][4], bf[4][2];
#pragma unroll
            for (int mi = 0; mi < 2; mi++) {
                int rb = wm2 * 32 + mi * 16;
                uint2 lo = *(const uint2*)&Ps[(rb + gid)     * 136 + kk + tig * 2];
                uint2 hi = *(const uint2*)&Ps[(rb + gid + 8) * 136 + kk + tig * 2];
                af[mi][0] = lo.x; af[mi][1] = hi.x; af[mi][2] = lo.y; af[mi][3] = hi.y;
            }
#pragma unroll
            for (int ni = 0; ni < 4; ni++) {
                int cb = wn2 * 32 + ni * 8;
                bf[ni][0] = Vs[(kk + tig)     * 72 + cb + gid];
                bf[ni][1] = Vs[(kk + tig + 4) * 72 + cb + gid];
            }
#pragma unroll
            for (int mi = 0; mi < 2; mi++)
#pragma unroll
                for (int ni = 0; ni < 4; ni++) mma8(acco[mi][ni], af[mi], bf[ni]);
        }
    }

    // ---- rowsum -> 1/l  (S ownership: wn in 0..3, rows wm*64+mi*16+gid+hl*8)
    __syncthreads();
#pragma unroll
    for (int mi = 0; mi < 4; mi++)
#pragma unroll
        for (int hl = 0; hl < 2; hl++) {
            float v = lsum[mi][hl];
            v += __shfl_xor_sync(~0u, v, 1);
            v += __shfl_xor_sync(~0u, v, 2);
            if (tig == 0) red[wn * 128 + wm * 64 + mi * 16 + gid + hl * 8] = v;
        }
    __syncthreads();
    if (tid < 128) {
        float inv = 1.f / (red[tid] + red[128 + tid] + red[256 + tid] + red[384 + tid]);
        sm_inv[tid] = inv;
        g_linv[(size_t)bh * TQ + m0 + tid] = inv;
    }
    __syncthreads();

    // ---- O normalize, tf32-round, PERMUTED store -> g_x (PV ownership)
#pragma unroll
    for (int mi = 0; mi < 2; mi++)
#pragma unroll
        for (int hl = 0; hl < 2; hl++) {
            int row = wm2 * 32 + mi * 16 + gid + hl * 8;
            float inv = sm_inv[row];
#pragma unroll
            for (int ni = 0; ni < 4; ni++) {
                int c = wn2 * 32 + ni * 8 + tig * 2;
                int j0 = (c & ~7) + ((c & 3) << 1) + ((c >> 2) & 1);
                float* xr = &g_x[((size_t)bh * TQ + m0 + row) * DH];
                xr[j0]     = roundtf(acco[mi][ni][hl * 2] * inv);
                xr[j0 + 2] = roundtf(acco[mi][ni][hl * 2 + 1] * inv);
            }
        }
}

// ---------------------------------------------------------------------------
extern "C" void kernel_launch(void* const* d_in, const int* in_sizes, int n_in,
                              void* d_out, int out_size)
{
    const float* query = (const float*)d_in[0];
    const float* key   = (const float*)d_in[1];
    const float* value = (const float*)d_in[2];
    const unsigned char* mask = (const unsigned char*)d_in[3];
    const float* Wq = (const float*)d_in[4];
    const float* bq = (const float*)d_in[5];
    const float* Wk = (const float*)d_in[6];
    const float* bk = (const float*)d_in[7];
    const float* Wv = (const float*)d_in[8];
    const float* bv = (const float*)d_in[9];
    const float* Wo = (const float*)d_in[10];
    const float* bo = (const float*)d_in[11];

    float* out_x = (float*)d_out;                       // [2048,4,1024]
    float* attn  = out_x + (size_t)TQ * BSZ * CDIM;     // [64,2048,2048]

    cudaFuncSetAttribute(attn_fused_kernel,
                         cudaFuncAttributeMaxDynamicSharedMemorySize, AT_SMEM);
    cudaFuncSetAttribute(qkv_proj_kernel,
                         cudaFuncAttributeMaxDynamicSharedMemorySize, PROJ_SMEM);
    cudaFuncSetAttribute(epilogue_kernel,
                         cudaFuncAttributeMaxDynamicSharedMemorySize, PROJ_SMEM);

    round_inputs_kernel<<<dim3(MPROJ, 1, 3), 256>>>(query, key, value);
    round_w_kernel<<<dim3(32, 32, 4), dim3(32, 8)>>>(Wq, Wk, Wv, Wo);
    qkv_proj_kernel<<<dim3(8, 64, 3), 256, PROJ_SMEM>>>(bq, bk, bv);
    attn_fused_kernel<<<dim3(16, 64), 256, AT_SMEM>>>(mask, attn);
    epilogue_kernel<<<dim3(512 * 33), 256, PROJ_SMEM>>>(bo, out_x, attn);
}

// round 17
// speedup vs baseline: 1.0041x; 1.0031x over previous
#include <cuda_runtime.h>
#include <cstdint>
#include <math.h>

// ---------------------------------------------------------------------------
// Round 14: attn -> 8 warps / 256 threads. S warp grid 2(m)x4(n), PV grid
// 4(m)x2(n): cuts K-fragment redundancy 4->2 and Ps-fragment redundancy 4->2
// (-192KB smem reads per tile, ~20% of all L1 bytes). Everything else = r13.
// ---------------------------------------------------------------------------

constexpr int TQ  = 2048;
constexpr int TK  = 2048;
constexpr int BSZ = 4;
constexpr int CDIM = 1024;
constexpr int H   = 16;
constexpr int DH  = 64;
constexpr int BH  = BSZ * H;            // 64
constexpr int MPROJ = TQ * BSZ;         // 8192

__device__ __align__(16) float g_aq[(size_t)MPROJ * CDIM];     // perm+rounded
__device__ __align__(16) float g_ak[(size_t)MPROJ * CDIM];
__device__ __align__(16) float g_av[(size_t)MPROJ * CDIM];
__device__ __align__(16) float g_w[4][(size_t)CDIM * CDIM];    // [n][p(k)] rounded
__device__ __align__(16) float g_q[(size_t)BH * TQ * DH];      // rounded
__device__ __align__(16) float g_k[(size_t)BH * TK * DH];
__device__ __align__(16) float g_v[(size_t)BH * TK * DH];
__device__ __align__(16) float g_x[(size_t)BH * TQ * DH];      // perm+rounded
__device__ float g_linv[(size_t)BH * TQ];

__device__ __forceinline__ unsigned f2tf(float x) {
    unsigned r; asm("cvt.rna.tf32.f32 %0, %1;" : "=r"(r) : "f"(x)); return r;
}
__device__ __forceinline__ float roundtf(float x) {
    return __uint_as_float(f2tf(x));
}
__device__ __forceinline__ void mma8(float* d, const unsigned* a, const unsigned* b) {
    asm volatile(
        "mma.sync.aligned.m16n8k8.row.col.f32.tf32.tf32.f32 "
        "{%0,%1,%2,%3},{%4,%5,%6,%7},{%8,%9},{%0,%1,%2,%3};"
        : "+f"(d[0]), "+f"(d[1]), "+f"(d[2]), "+f"(d[3])
        : "r"(a[0]), "r"(a[1]), "r"(a[2]), "r"(a[3]), "r"(b[0]), "r"(b[1]));
}
__device__ __forceinline__ unsigned sptr(const void* p) {
    return (unsigned)__cvta_generic_to_shared(p);
}
#define CP16(dst_u32, src_ptr) \
    asm volatile("cp.async.cg.shared.global [%0], [%1], 16;" :: "r"(dst_u32), "l"(src_ptr))
#define CP_COMMIT() asm volatile("cp.async.commit_group;")

// ---------------------------------------------------------------------------
// prep kernels
// ---------------------------------------------------------------------------
__global__ __launch_bounds__(256)
void round_inputs_kernel(const float* __restrict__ q, const float* __restrict__ k,
                         const float* __restrict__ v)
{
    const int z = blockIdx.z;
    const float4* src = (const float4*)((z == 0) ? q : (z == 1) ? k : v);
    float* dst = (z == 0) ? g_aq : (z == 1) ? g_ak : g_av;
    size_t idx = (size_t)blockIdx.x * 256 + threadIdx.x;
    float4 a = src[idx];
    size_t m = idx >> 8;
    int kk = (int)(idx & 255) * 4;
    size_t base = m * CDIM + (kk & ~7) + ((kk >> 2) & 1);
    dst[base + 0] = roundtf(a.x);
    dst[base + 2] = roundtf(a.y);
    dst[base + 4] = roundtf(a.z);
    dst[base + 6] = roundtf(a.w);
}

__global__ __launch_bounds__(256)
void round_w_kernel(const float* __restrict__ W0, const float* __restrict__ W1,
                    const float* __restrict__ W2, const float* __restrict__ W3)
{
    __shared__ float t[32][33];
    const int z = blockIdx.z;
    const float* W = (z == 0) ? W0 : (z == 1) ? W1 : (z == 2) ? W2 : W3;
    float* out = g_w[z];
    const int bx = blockIdx.x * 32;   // n base
    const int by = blockIdx.y * 32;   // k base
    const int tx = threadIdx.x, ty = threadIdx.y;
#pragma unroll
    for (int j = 0; j < 4; j++)
        t[ty + j * 8][tx] = W[(size_t)(by + ty + j * 8) * CDIM + bx + tx];
    __syncthreads();
    const int pk = (tx & ~7) | ((tx & 3) << 1) | ((tx >> 2) & 1);
#pragma unroll
    for (int j = 0; j < 4; j++)
        out[(size_t)(bx + ty + j * 8) * CDIM + by + pk] = roundtf(t[tx][ty + j * 8]);
}

// ---------------------------------------------------------------------------
// proj mma core (stride 40, conflict-free LDS.64)
// ---------------------------------------------------------------------------
__device__ __forceinline__
void proj_mma_step(float acc[4][4][4], const unsigned* AsF, const unsigned* BsF,
                   int wm, int wn, int gid, int tig)
{
#pragma unroll
    for (int kk = 0; kk < 32; kk += 8) {
        unsigned af[4][4], bf[4][2];
#pragma unroll
        for (int mi = 0; mi < 4; mi++) {
            int rb = wm * 64 + mi * 16;
            uint2 lo = *(const uint2*)&AsF[(rb + gid)     * 40 + kk + tig * 2];
            uint2 hi = *(const uint2*)&AsF[(rb + gid + 8) * 40 + kk + tig * 2];
            af[mi][0] = lo.x; af[mi][1] = hi.x; af[mi][2] = lo.y; af[mi][3] = hi.y;
        }
#pragma unroll
        for (int ni = 0; ni < 4; ni++) {
            int cb = wn * 32 + ni * 8;
            uint2 u = *(const uint2*)&BsF[(cb + gid) * 40 + kk + tig * 2];
            bf[ni][0] = u.x; bf[ni][1] = u.y;
        }
#pragma unroll
        for (int mi = 0; mi < 4; mi++)
#pragma unroll
            for (int ni = 0; ni < 4; ni++) mma8(acc[mi][ni], af[mi], bf[ni]);
    }
}

template<bool GATHER>
__device__ __forceinline__
void proj_issue(unsigned asm_, unsigned bsm_, const float* __restrict__ A,
                const float* __restrict__ Wt, int m0, int n0, int k0, int tid)
{
#pragma unroll
    for (int i = 0; i < 4; i++) {
        int li = tid + i * 256;
        int r = li >> 3, c = li & 7;
        const float* src;
        if (!GATHER) {
            src = A + (size_t)(m0 + r) * CDIM + k0 + c * 4;
        } else {
            int m = m0 + r, t = m >> 2, b = m & 3;
            int k = k0 + c * 4, h = k >> 6, d = k & 63;
            src = g_x + (((size_t)(b * H + h)) * TQ + t) * DH + d;
        }
        CP16(asm_ + (r * 40 + c * 4) * 4, src);
    }
#pragma unroll
    for (int i = 0; i < 4; i++) {
        int li = tid + i * 256;
        int r = li >> 3, c = li & 7;
        CP16(bsm_ + (r * 40 + c * 4) * 4, Wt + (size_t)(n0 + r) * CDIM + k0 + c * 4);
    }
    CP_COMMIT();
}

struct ProjSmem { unsigned As[2][128 * 40]; unsigned Bs[2][128 * 40]; };
constexpr int PROJ_SMEM = sizeof(ProjSmem);   // 81920

template<bool GATHER>
__device__ __forceinline__
void proj_tile(ProjSmem* sm, const float* __restrict__ A, const float* __restrict__ Wt,
               float acc[4][4][4], int m0, int n0, int tid,
               int wm, int wn, int gid, int tig)
{
    proj_issue<GATHER>(sptr(sm->As[0]), sptr(sm->Bs[0]), A, Wt, m0, n0, 0, tid);
    for (int it = 0; it < 32; it++) {
        if (it < 31)
            proj_issue<GATHER>(sptr(sm->As[(it + 1) & 1]), sptr(sm->Bs[(it + 1) & 1]),
                               A, Wt, m0, n0, (it + 1) * 32, tid);
        if (it < 31) asm volatile("cp.async.wait_group 1;");
        else         asm volatile("cp.async.wait_group 0;");
        __syncthreads();
        proj_mma_step(acc, sm->As[it & 1], sm->Bs[it & 1], wm, wn, gid, tig);
        __syncthreads();
    }
}

__global__ __launch_bounds__(256, 2)
void qkv_proj_kernel(const float* __restrict__ bq, const float* __restrict__ bk,
                     const float* __restrict__ bv)
{
    extern __shared__ char smraw[];
    ProjSmem* sm = (ProjSmem*)smraw;
    const int z = blockIdx.z;
    const float* A    = (z == 0) ? g_aq : (z == 1) ? g_ak : g_av;
    const float* Wt   = g_w[z];
    const float* bias = (z == 0) ? bq : (z == 1) ? bk : bv;
    float* dst        = (z == 0) ? g_q : (z == 1) ? g_k : g_v;
    const float scale = (z == 0) ? 0.125f : 1.f;

    const int tid = threadIdx.x, lane = tid & 31, wid = tid >> 5;
    const int gid = lane >> 2, tig = lane & 3;
    const int wm = wid >> 2, wn = wid & 3;
    const int m0 = blockIdx.y * 128, n0 = blockIdx.x * 128;

    float acc[4][4][4] = {};
    proj_tile<false>(sm, A, Wt, acc, m0, n0, tid, wm, wn, gid, tig);

#pragma unroll
    for (int mi = 0; mi < 4; mi++)
#pragma unroll
        for (int hl = 0; hl < 2; hl++) {
            int m = m0 + wm * 64 + mi * 16 + gid + hl * 8;
#pragma unroll
            for (int ni = 0; ni < 4; ni++) {
                int n = n0 + wn * 32 + ni * 8 + tig * 2;
                float2 v;
                v.x = roundtf((acc[mi][ni][hl * 2 + 0] + bias[n + 0]) * scale);
                v.y = roundtf((acc[mi][ni][hl * 2 + 1] + bias[n + 1]) * scale);
                int t = m >> 2, b = m & 3, h = n >> 6, d = n & 63;
                *(float2*)&dst[(((size_t)(b * H + h)) * TQ + t) * DH + d] = v;
            }
        }
}

// ---------------------------------------------------------------------------
// Heterogeneous epilogue: r==0 -> double-buffered out_proj tile; r>0 ->
// rescale 8 attn rows.
// ---------------------------------------------------------------------------
__global__ __launch_bounds__(256)
void epilogue_kernel(const float* __restrict__ bias, float* __restrict__ Out,
                     float* __restrict__ attn)
{
    const int g = blockIdx.x;
    const int p = g / 33, r = g % 33;
    if (r == 0) {
        extern __shared__ char smraw[];
        ProjSmem* sm = (ProjSmem*)smraw;
        const int tid = threadIdx.x, lane = tid & 31, wid = tid >> 5;
        const int gid = lane >> 2, tig = lane & 3;
        const int wm = wid >> 2, wn = wid & 3;
        const int m0 = (p >> 3) * 128, n0 = (p & 7) * 128;

        float acc[4][4][4] = {};
        proj_tile<true>(sm, nullptr, g_w[3], acc, m0, n0, tid, wm, wn, gid, tig);

#pragma unroll
        for (int mi = 0; mi < 4; mi++)
#pragma unroll
            for (int hl = 0; hl < 2; hl++) {
                int m = m0 + wm * 64 + mi * 16 + gid + hl * 8;
#pragma unroll
                for (int ni = 0; ni < 4; ni++) {
                    int n = n0 + wn * 32 + ni * 8 + tig * 2;
                    float2 v;
                    v.x = acc[mi][ni][hl * 2 + 0] + bias[n + 0];
                    v.y = acc[mi][ni][hl * 2 + 1] + bias[n + 1];
                    *(float2*)&Out[(size_t)m * CDIM + n] = v;
                }
            }
    } else {
        const size_t row0 = ((size_t)p * 32 + (r - 1)) * 8;
        const int tid = threadIdx.x;
#pragma unroll
        for (int rr = 0; rr < 8; rr++) {
            const size_t row = row0 + rr;
            const float inv = g_linv[row];
            float4* pr = (float4*)(attn + row * (size_t)TK);
            float4 v0 = pr[tid], v1 = pr[tid + 256];
            v0.x *= inv; v0.y *= inv; v0.z *= inv; v0.w *= inv;
            v1.x *= inv; v1.y *= inv; v1.z *= inv; v1.w *= inv;
            pr[tid] = v0; pr[tid + 256] = v1;
        }
    }
}

// ---------------------------------------------------------------------------
// attn_fused (256 threads, 8 warps).
// S phase: warp grid 2(m) x 4(n), warp tile 64m x 32n  (Q x4, K x2 redund.)
// PV phase: warp grid 4(m) x 2(n), warp tile 32m x 32n (Ps x2, V x4 redund.)
// Strides: Qs 72, Ks 68, Vs 72, Ps 136 (all conflict-free per r12/r13 model).
// smem u32 map:
//   Qs 0..9216 | Ks0 9216..17920 | Ks1 17920..26624 | Vs 26624..35840 |
//   Ps 35840..53248 | mskAll 53248..55296 | red 55296..55808 | sm_inv ..55936
// ---------------------------------------------------------------------------
constexpr int AT_SMEM = 55936 * 4;   // 223744 B

__global__ __launch_bounds__(256, 1)
void attn_fused_kernel(const unsigned char* __restrict__ mask,
                       float* __restrict__ attn)
{
    extern __shared__ unsigned smem_u[];
    unsigned* Qs  = smem_u;                        // [128][72] perm tf32
    unsigned* Ks0 = smem_u + 9216;                 // [n:128][d:64] s68
    unsigned* Ks1 = smem_u + 17920;
    unsigned* Vs  = smem_u + 26624;                // [n:128][d:64] s72
    unsigned* Ps  = smem_u + 35840;                // [128][136] tf32 perm
    float* mskAll = (float*)(smem_u + 53248);      // [2048]
    float* red    = (float*)(smem_u + 55296);      // [4][128]
    float* sm_inv = (float*)(smem_u + 55808);

    const int tid = threadIdx.x, lane = tid & 31, wid = tid >> 5;
    const int gid = lane >> 2, tig = lane & 3;
    const int wm = wid >> 2, wn = wid & 3;         // S: 2 x 4
    const int wm2 = wid >> 1, wn2 = wid & 1;       // PV: 4 x 2
    const int m0 = blockIdx.x * 128, bh = blockIdx.y, b = bh >> 4;

    const float* kbase = g_k + (size_t)bh * TK * DH;
    const float* vbase = g_v + (size_t)bh * TK * DH;

#pragma unroll
    for (int i = 0; i < 8; i++) {
        int li = tid + i * 256;
        int r = li >> 4, c = li & 15;
        uint4 a = *(const uint4*)&g_q[((size_t)bh * TQ + m0 + r) * DH + c * 4];
        unsigned* q = &Qs[r * 72 + (c >> 1) * 8 + (c & 1)];
        q[0] = a.x; q[2] = a.y; q[4] = a.z; q[6] = a.w;
    }
#pragma unroll
    for (int i = 0; i < 8; i++) {
        int idx = tid + i * 256;
        mskAll[idx] = mask[(size_t)b * TK + idx] ? -INFINITY : 0.f;
    }
    {
        const unsigned ksm = sptr(Ks0);
#pragma unroll
        for (int j = 0; j < 8; j++) {
            int li = tid + j * 256;
            int r = li >> 4, c16 = li & 15;
            CP16(ksm + (r * 68 + c16 * 4) * 4, kbase + r * 64 + c16 * 4);
        }
        CP_COMMIT();
    }

    float acco[2][4][4] = {};     // PV: 2 mi x 4 ni (32m x 32n warp tile)
    float lsum[4][2] = {};        // S: 4 mi x 2 hl
    const int perm0 = ((2 * tig) & 3) * 2 + (tig >> 1);

    for (int nt = 0; nt < 16; nt++) {
        const int n0 = nt * 128;
        __syncthreads();

        {
            const unsigned vsm = sptr(Vs);
#pragma unroll
            for (int j = 0; j < 8; j++) {
                int li = tid + j * 256;
                int r = li >> 4, c16 = li & 15;
                CP16(vsm + (r * 72 + c16 * 4) * 4, vbase + (size_t)(n0 + r) * 64 + c16 * 4);
            }
            CP_COMMIT();
        }
        if (nt < 15) {
            unsigned* Kn = ((nt + 1) & 1) ? Ks1 : Ks0;
            const unsigned ksm = sptr(Kn);
#pragma unroll
            for (int j = 0; j < 8; j++) {
                int li = tid + j * 256;
                int r = li >> 4, c16 = li & 15;
                CP16(ksm + (r * 68 + c16 * 4) * 4,
                     kbase + (size_t)(n0 + 128 + r) * 64 + c16 * 4);
            }
            CP_COMMIT();
        }

        if (nt < 15) asm volatile("cp.async.wait_group 2;");
        else         asm volatile("cp.async.wait_group 1;");
        __syncthreads();

        const unsigned* Ksu = (nt & 1) ? Ks1 : Ks0;

        // ---- S = Q @ K^T  (warp tile 64m x 32n)
        float acc[4][4][4] = {};
#pragma unroll
        for (int kk = 0; kk < 64; kk += 8) {
            unsigned af[4][4], bf[4][2];
#pragma unroll
            for (int mi = 0; mi < 4; mi++) {
                int rb = wm * 64 + mi * 16;
                uint2 lo = *(const uint2*)&Qs[(rb + gid)     * 72 + kk + tig * 2];
                uint2 hi = *(const uint2*)&Qs[(rb + gid + 8) * 72 + kk + tig * 2];
                af[mi][0] = lo.x; af[mi][1] = hi.x; af[mi][2] = lo.y; af[mi][3] = hi.y;
            }
#pragma unroll
            for (int ni = 0; ni < 4; ni++) {
                int cb = wn * 32 + ni * 8;
                bf[ni][0] = Ksu[(cb + gid) * 68 + kk + tig];
                bf[ni][1] = Ksu[(cb + gid) * 68 + kk + tig + 4];
            }
#pragma unroll
            for (int mi = 0; mi < 4; mi++)
#pragma unroll
                for (int ni = 0; ni < 4; ni++) mma8(acc[mi][ni], af[mi], bf[ni]);
        }

        float mk[4][2];
#pragma unroll
        for (int ni = 0; ni < 4; ni++) {
            float2 mm = *(const float2*)&mskAll[n0 + wn * 32 + ni * 8 + 2 * tig];
            mk[ni][0] = mm.x; mk[ni][1] = mm.y;
        }

        // ---- E = exp(S+mask): attn write (unnormalized), rowsum, Ps stage
#pragma unroll
        for (int mi = 0; mi < 4; mi++) {
            int rb = wm * 64 + mi * 16;
#pragma unroll
            for (int hl = 0; hl < 2; hl++) {
                int row = rb + gid + hl * 8;
                float* arow = attn + ((size_t)bh * TQ + m0 + row) * TK + n0;
                float ls = 0.f;
#pragma unroll
                for (int ni = 0; ni < 4; ni++) {
                    int cb = wn * 32 + ni * 8;
                    float p0 = __expf(acc[mi][ni][hl * 2]     + mk[ni][0]);
                    float p1 = __expf(acc[mi][ni][hl * 2 + 1] + mk[ni][1]);
                    *(float2*)&arow[cb + 2 * tig] = make_float2(p0, p1);
                    unsigned* pp = &Ps[row * 136 + cb + perm0];
                    pp[0] = f2tf(p0); pp[2] = f2tf(p1);
                    ls += p0 + p1;
                }
                lsum[mi][hl] += ls;
            }
        }

        if (nt < 15) asm volatile("cp.async.wait_group 1;");
        else         asm volatile("cp.async.wait_group 0;");
        __syncthreads();

        // ---- O += E @ V   (warp tile 32m x 32n, k = 128)
#pragma unroll
        for (int kk = 0; kk < 128; kk += 8) {
            unsigned af[2][4], bf[4][2];
#pragma unroll
            for (int mi = 0; mi < 2; mi++) {
                int rb = wm2 * 32 + mi * 16;
                uint2 lo = *(const uint2*)&Ps[(rb + gid)     * 136 + kk + tig * 2];
                uint2 hi = *(const uint2*)&Ps[(rb + gid + 8) * 136 + kk + tig * 2];
                af[mi][0] = lo.x; af[mi][1] = hi.x; af[mi][2] = lo.y; af[mi][3] = hi.y;
            }
#pragma unroll
            for (int ni = 0; ni < 4; ni++) {
                int cb = wn2 * 32 + ni * 8;
                bf[ni][0] = Vs[(kk + tig)     * 72 + cb + gid];
                bf[ni][1] = Vs[(kk + tig + 4) * 72 + cb + gid];
            }
#pragma unroll
            for (int mi = 0; mi < 2; mi++)
#pragma unroll
                for (int ni = 0; ni < 4; ni++) mma8(acco[mi][ni], af[mi], bf[ni]);
        }
    }

    // ---- rowsum -> 1/l  (S ownership: wn in 0..3, rows wm*64+mi*16+gid+hl*8)
    __syncthreads();
#pragma unroll
    for (int mi = 0; mi < 4; mi++)
#pragma unroll
        for (int hl = 0; hl < 2; hl++) {
            float v = lsum[mi][hl];
            v += __shfl_xor_sync(~0u, v, 1);
            v += __shfl_xor_sync(~0u, v, 2);
            if (tig == 0) red[wn * 128 + wm * 64 + mi * 16 + gid + hl * 8] = v;
        }
    __syncthreads();
    if (tid < 128) {
        float inv = 1.f / (red[tid] + red[128 + tid] + red[256 + tid] + red[384 + tid]);
        sm_inv[tid] = inv;
        g_linv[(size_t)bh * TQ + m0 + tid] = inv;
    }
    __syncthreads();

    // ---- O normalize, tf32-round, PERMUTED store -> g_x (PV ownership)
#pragma unroll
    for (int mi = 0; mi < 2; mi++)
#pragma unroll
        for (int hl = 0; hl < 2; hl++) {
            int row = wm2 * 32 + mi * 16 + gid + hl * 8;
            float inv = sm_inv[row];
#pragma unroll
            for (int ni = 0; ni < 4; ni++) {
                int c = wn2 * 32 + ni * 8 + tig * 2;
                int j0 = (c & ~7) + ((c & 3) << 1) + ((c >> 2) & 1);
                float* xr = &g_x[((size_t)bh * TQ + m0 + row) * DH];
                xr[j0]     = roundtf(acco[mi][ni][hl * 2] * inv);
                xr[j0 + 2] = roundtf(acco[mi][ni][hl * 2 + 1] * inv);
            }
        }
}

// ---------------------------------------------------------------------------
extern "C" void kernel_launch(void* const* d_in, const int* in_sizes, int n_in,
                              void* d_out, int out_size)
{
    const float* query = (const float*)d_in[0];
    const float* key   = (const float*)d_in[1];
    const float* value = (const float*)d_in[2];
    const unsigned char* mask = (const unsigned char*)d_in[3];
    const float* Wq = (const float*)d_in[4];
    const float* bq = (const float*)d_in[5];
    const float* Wk = (const float*)d_in[6];
    const float* bk = (const float*)d_in[7];
    const float* Wv = (const float*)d_in[8];
    const float* bv = (const float*)d_in[9];
    const float* Wo = (const float*)d_in[10];
    const float* bo = (const float*)d_in[11];

    float* out_x = (float*)d_out;                       // [2048,4,1024]
    float* attn  = out_x + (size_t)TQ * BSZ * CDIM;     // [64,2048,2048]

    cudaFuncSetAttribute(attn_fused_kernel,
                         cudaFuncAttributeMaxDynamicSharedMemorySize, AT_SMEM);
    cudaFuncSetAttribute(qkv_proj_kernel,
                         cudaFuncAttributeMaxDynamicSharedMemorySize, PROJ_SMEM);
    cudaFuncSetAttribute(epilogue_kernel,
                         cudaFuncAttributeMaxDynamicSharedMemorySize, PROJ_SMEM);

    round_inputs_kernel<<<dim3(MPROJ, 1, 3), 256>>>(query, key, value);
    round_w_kernel<<<dim3(32, 32, 4), dim3(32, 8)>>>(Wq, Wk, Wv, Wo);
    qkv_proj_kernel<<<dim3(8, 64, 3), 256, PROJ_SMEM>>>(bq, bk, bv);
    attn_fused_kernel<<<dim3(16, 64), 256, AT_SMEM>>>(mask, attn);
    epilogue_kernel<<<dim3(512 * 33), 256, PROJ_SMEM>>>(bo, out_x, attn);
}